// round 9
// baseline (speedup 1.0000x reference)
#include <cuda_runtime.h>

#define R_NUM 4096
#define L_NUM 32
#define C_NUM 512
#define CC    (C_NUM*C_NUM)
#define H_NUM 4
#define DH    128
#define NT    512
#define LD    516          // smem row stride (floats), 16B-aligned rows
#define LN_EPS 1e-5f

typedef unsigned long long u64;

struct Smem {
    float  X[L_NUM * LD];            // 66048 B
    float  A[L_NUM * LD];
    float  B[L_NUM * LD];
    float  S[H_NUM * L_NUM * L_NUM]; // 16384 B, overlaid with PMA vectors after SABs
    float4 Wp[2 * C_NUM];            // 16384 B: W panel, [kq][j] (kq in {0,1}, 4 k each)
    float  red[40];
};

__device__ __forceinline__ void ffma2(u64& d, u64 a, u64 b) {
    // packed f32x2 FMA: d.lo += a.lo*b.lo ; d.hi += a.hi*b.hi
    asm("fma.rn.f32x2 %0, %1, %2, %0;" : "+l"(d) : "l"(a), "l"(b));
}
__device__ __forceinline__ float hadd2(u64 v) {
    return __uint_as_float((unsigned)v) + __uint_as_float((unsigned)(v >> 32));
}
__device__ __forceinline__ float warp_sum(float v) {
#pragma unroll
    for (int o = 16; o; o >>= 1) v += __shfl_xor_sync(0xffffffffu, v, o);
    return v;
}

// Out[32][512] = Xs[32][512] @ Wg[512,512]^T + bg. Xs/Out smem (stride LD), Wg/bg global.
// 512 threads, per-thread tile 8 rows x 4 cols, k-packed f32x2 accumulators.
// W panel (8 k) staged via smem with register prefetch of the next panel.
__device__ __noinline__ void gemm32(const float* __restrict__ Xs, const float* __restrict__ Wg,
                                    const float* __restrict__ bg, float* __restrict__ Out,
                                    float4* __restrict__ Wp, int tid, bool relu)
{
    const int rg = tid >> 7;    // 0..3 -> rows rg*8..rg*8+7 (uniform per warp)
    const int cg = tid & 127;   // cols cg + 128*jj
    u64 acc[8][4];
#pragma unroll
    for (int a = 0; a < 8; a++)
#pragma unroll
        for (int b = 0; b < 4; b++) acc[a][b] = 0ull;

    // prefetch panel 0: thread tid owns row j=tid, k[0..7] (two float4)
    const float* wrow = Wg + (size_t)tid * C_NUM;
    float4 pw0 = *reinterpret_cast<const float4*>(wrow + 0);
    float4 pw1 = *reinterpret_cast<const float4*>(wrow + 4);

    for (int k0 = 0; k0 < C_NUM; k0 += 8) {
        __syncthreads();                       // previous panel consumed
        Wp[tid]       = pw0;                   // Wp[kq*512 + j], kq=0
        Wp[tid + 512] = pw1;                   // kq=1
        if (k0 + 8 < C_NUM) {                  // prefetch next panel (hidden by compute)
            pw0 = *reinterpret_cast<const float4*>(wrow + k0 + 8);
            pw1 = *reinterpret_cast<const float4*>(wrow + k0 + 12);
        }
        __syncthreads();                       // panel ready
        const ulonglong2* WpU = reinterpret_cast<const ulonglong2*>(Wp);
#pragma unroll
        for (int kq = 0; kq < 2; kq++) {
            ulonglong2 xu[8];
#pragma unroll
            for (int ii = 0; ii < 8; ii++)
                xu[ii] = *reinterpret_cast<const ulonglong2*>(Xs + (rg * 8 + ii) * LD + k0 + kq * 4);
#pragma unroll
            for (int jj = 0; jj < 4; jj++) {
                ulonglong2 wu = WpU[kq * C_NUM + cg + 128 * jj];
#pragma unroll
                for (int ii = 0; ii < 8; ii++) {
                    ffma2(acc[ii][jj], xu[ii].x, wu.x);
                    ffma2(acc[ii][jj], xu[ii].y, wu.y);
                }
            }
        }
    }
#pragma unroll
    for (int jj = 0; jj < 4; jj++) {
        int j = cg + 128 * jj;
        float bj = bg[j];
#pragma unroll
        for (int ii = 0; ii < 8; ii++) {
            float v = hadd2(acc[ii][jj]) + bj;
            if (relu) v = fmaxf(v, 0.f);
            Out[(rg * 8 + ii) * LD + j] = v;
        }
    }
    __syncthreads();
}

// scores[h][i][j] = dot(Q[i,h*128:],K[j,:])/sqrt(128); mask j>=ylen; softmax over j.
__device__ __noinline__ void sab_scores_softmax(const float* __restrict__ Q, const float* __restrict__ K,
                                                float* __restrict__ S, int ylen, int tid)
{
    const float scale = 0.08838834764831845f;  // 1/sqrt(128)
#pragma unroll
    for (int it = 0; it < 8; it++) {
        int idx = tid + it * NT;               // h*1024 + i*32 + j
        int h = idx >> 10, i = (idx >> 5) & 31, j = idx & 31;
        const ulonglong2* q2 = reinterpret_cast<const ulonglong2*>(Q + i * LD + h * DH);
        const ulonglong2* k2 = reinterpret_cast<const ulonglong2*>(K + j * LD + h * DH);
        u64 a0 = 0ull, a1 = 0ull;
#pragma unroll
        for (int d = 0; d < DH / 4; d++) {
            ulonglong2 qa = q2[d], kb = k2[d];
            ffma2(a0, qa.x, kb.x);
            ffma2(a1, qa.y, kb.y);
        }
        S[idx] = (hadd2(a0) + hadd2(a1)) * scale;
    }
    __syncthreads();
    if (tid < H_NUM * L_NUM) {
        float* row = S + tid * L_NUM;          // tid = h*32 + i
        float mx = -1e30f;
        for (int j = 0; j < ylen; j++) mx = fmaxf(mx, row[j]);
        float sum = 0.f;
        for (int j = 0; j < L_NUM; j++) {
            float e = (j < ylen) ? __expf(row[j] - mx) : 0.f;
            row[j] = e; sum += e;
        }
        float inv = 1.f / sum;
        for (int j = 0; j < L_NUM; j++) row[j] *= inv;
    }
    __syncthreads();
}

// Out[i][c] = sum_j S[h(c)][i][j] * V[j][c]
__device__ __noinline__ void attn_v(const float* __restrict__ S, const float* __restrict__ V,
                                    float* __restrict__ Out, int ylen, int tid)
{
    const int rg = tid >> 7, cg = tid & 127;
    float acc[8][4];
#pragma unroll
    for (int a = 0; a < 8; a++)
#pragma unroll
        for (int b = 0; b < 4; b++) acc[a][b] = 0.f;

    for (int jk = 0; jk < ylen; jk++) {
        float vv[4];
#pragma unroll
        for (int jj = 0; jj < 4; jj++) vv[jj] = V[jk * LD + cg + 128 * jj];
        float sv[H_NUM][8];
#pragma unroll
        for (int h = 0; h < H_NUM; h++)
#pragma unroll
            for (int ii = 0; ii < 8; ii++)
                sv[h][ii] = S[h * (L_NUM * L_NUM) + (rg * 8 + ii) * L_NUM + jk];
#pragma unroll
        for (int jj = 0; jj < 4; jj++) {       // h = (cg+128*jj)>>7 == jj (cg<128)
#pragma unroll
            for (int ii = 0; ii < 8; ii++)
                acc[ii][jj] = fmaf(sv[jj][ii], vv[jj], acc[ii][jj]);
        }
    }
#pragma unroll
    for (int jj = 0; jj < 4; jj++)
#pragma unroll
        for (int ii = 0; ii < 8; ii++)
            Out[(rg * 8 + ii) * LD + cg + 128 * jj] = acc[ii][jj];
    __syncthreads();
}

// X[i] = LN(X[i] + (i<xm ? Y[i] : 0)) rowwise with gamma/beta
__device__ __noinline__ void sab_add_ln(float* __restrict__ X, const float* __restrict__ Y,
                                        const float* __restrict__ g, const float* __restrict__ b,
                                        int xm, int tid)
{
    const int w = tid >> 5, lane = tid & 31;
    for (int row = w; row < L_NUM; row += 16) {
        const float* yr = Y + row * LD;
        float* xr = X + row * LD;
        bool useY = row < xm;
        float s = 0.f, s2 = 0.f;
        for (int c = lane; c < C_NUM; c += 32) {
            float v = xr[c] + (useY ? yr[c] : 0.f);
            s += v; s2 += v * v;
        }
        s = warp_sum(s); s2 = warp_sum(s2);
        float mean = s * (1.f / C_NUM);
        float var = s2 * (1.f / C_NUM) - mean * mean;
        float rstd = rsqrtf(var + LN_EPS);
        for (int c = lane; c < C_NUM; c += 32) {
            float v = xr[c] + (useY ? yr[c] : 0.f);
            xr[c] = (v - mean) * rstd * g[c] + b[c];
        }
    }
    __syncthreads();
}

__device__ __noinline__ void mab_sab(Smem* sm,
    const float* Wq, const float* Wk, const float* Wv, const float* Wo, const float* ffW,
    const float* bq, const float* bk, const float* bv, const float* bo, const float* ffb,
    const float* g1, const float* b1, const float* g2, const float* b2,
    int ylen, int xm, int tid)
{
    gemm32(sm->X, Wq, bq, sm->A, sm->Wp, tid, false);             // Q -> A
    gemm32(sm->X, Wk, bk, sm->B, sm->Wp, tid, false);             // K -> B
    sab_scores_softmax(sm->A, sm->B, sm->S, ylen, tid);           // attn -> S
    gemm32(sm->X, Wv, bv, sm->B, sm->Wp, tid, false);             // V -> B (K dead)
    attn_v(sm->S, sm->B, sm->A, ylen, tid);                       // attn@V -> A (Q dead)
    gemm32(sm->A, Wo, bo, sm->B, sm->Wp, tid, false);             // O -> B
    sab_add_ln(sm->X, sm->B, g1, b1, xm, tid);                    // X = LN(X + mask(O))
    gemm32(sm->X, ffW, ffb, sm->A, sm->Wp, tid, true);            // relu FF -> A
    sab_add_ln(sm->X, sm->A, g2, b2, L_NUM, tid);                 // X = LN(X + FF)
}

// out[j] = sum_k xin[k]*Wg[j][k] + bg[j]   (xin: smem [512]); one j per thread
__device__ __noinline__ void vec_gemm(const float* __restrict__ xin, const float* __restrict__ Wg,
                                      const float* __restrict__ bg, float* __restrict__ out,
                                      int tid, bool relu)
{
    const ulonglong2* x2 = reinterpret_cast<const ulonglong2*>(xin);
    int j = tid;                               // NT == C_NUM
    const ulonglong2* w2 = reinterpret_cast<const ulonglong2*>(Wg + (size_t)j * C_NUM);
    u64 a0 = 0ull, a1 = 0ull;
#pragma unroll 8
    for (int d = 0; d < C_NUM / 4; d++) {
        ulonglong2 w = w2[d], x = x2[d];
        ffma2(a0, w.x, x.x);
        ffma2(a1, w.y, x.y);
    }
    float v = hadd2(a0) + hadd2(a1) + bg[j];
    if (relu) v = fmaxf(v, 0.f);
    out[j] = v;
    __syncthreads();
}

// x = LN(x + y) over a single 512-vector (block-wide, 16 warps)
__device__ __noinline__ void vec_add_ln(float* __restrict__ x, const float* __restrict__ y,
                                        const float* __restrict__ g, const float* __restrict__ b,
                                        float* __restrict__ red, int tid)
{
    float s = 0.f, s2 = 0.f;
    for (int c = tid; c < C_NUM; c += NT) {
        float v = x[c] + y[c]; s += v; s2 += v * v;
    }
    s = warp_sum(s); s2 = warp_sum(s2);
    int w = tid >> 5, lane = tid & 31;
    if (lane == 0) { red[w] = s; red[16 + w] = s2; }
    __syncthreads();
    if (tid == 0) {
        float ts = 0, ts2 = 0;
        for (int i = 0; i < 16; i++) { ts += red[i]; ts2 += red[16 + i]; }
        float mean = ts * (1.f / C_NUM);
        float var = ts2 * (1.f / C_NUM) - mean * mean;
        red[32] = mean; red[33] = rsqrtf(var + LN_EPS);
    }
    __syncthreads();
    float mean = red[32], rstd = red[33];
    for (int c = tid; c < C_NUM; c += NT) {
        float v = x[c] + y[c];
        x[c] = (v - mean) * rstd * g[c] + b[c];
    }
    __syncthreads();
}

// PMA attention: q (smem [512]) over K=sm->A [32,512], V=sm->B; out -> outv [512]
__device__ __noinline__ void pma_attn(Smem* sm, const float* __restrict__ q,
                                      float* __restrict__ psc, float* __restrict__ outv,
                                      int ylen, int tid)
{
    const float scale = 0.08838834764831845f;
    if (tid < H_NUM * L_NUM) {
        int h = tid >> 5, j = tid & 31;
        if (j < ylen) {
            const ulonglong2* q2 = reinterpret_cast<const ulonglong2*>(q + h * DH);
            const ulonglong2* k2 = reinterpret_cast<const ulonglong2*>(sm->A + j * LD + h * DH);
            u64 a0 = 0ull, a1 = 0ull;
#pragma unroll
            for (int d = 0; d < DH / 4; d++) {
                ulonglong2 qa = q2[d], kb = k2[d];
                ffma2(a0, qa.x, kb.x);
                ffma2(a1, qa.y, kb.y);
            }
            psc[h * L_NUM + j] = (hadd2(a0) + hadd2(a1)) * scale;
        }
    }
    __syncthreads();
    if (tid < H_NUM) {
        float* row = psc + tid * L_NUM;
        float mx = -1e30f;
        for (int j = 0; j < ylen; j++) mx = fmaxf(mx, row[j]);
        float sum = 0.f;
        for (int j = 0; j < ylen; j++) { float e = __expf(row[j] - mx); row[j] = e; sum += e; }
        float inv = 1.f / sum;
        for (int j = 0; j < ylen; j++) row[j] *= inv;
    }
    __syncthreads();
    for (int c = tid; c < C_NUM; c += NT) {
        int h = c >> 7;
        float s = 0.f;
        for (int j = 0; j < ylen; j++) s = fmaf(psc[h * L_NUM + j], sm->B[j * LD + c], s);
        outv[c] = s;
    }
    __syncthreads();
}

__global__ void __launch_bounds__(NT, 1)
rxn_set_transformer_kernel(
    const float* __restrict__ emb, const int* __restrict__ gidx, const int* __restrict__ glen,
    const float* __restrict__ Wq, const float* __restrict__ Wk, const float* __restrict__ Wv,
    const float* __restrict__ Wo, const float* __restrict__ ffW,
    const float* __restrict__ bq, const float* __restrict__ bk, const float* __restrict__ bv,
    const float* __restrict__ bo, const float* __restrict__ ffb,
    const float* __restrict__ g1, const float* __restrict__ b1,
    const float* __restrict__ g2, const float* __restrict__ b2,
    const float* __restrict__ pW, const float* __restrict__ pb,
    const float* __restrict__ seed, float* __restrict__ out)
{
    extern __shared__ char smem_raw[];
    Smem* sm = reinterpret_cast<Smem*>(smem_raw);
    const int tid = threadIdx.x;
    const int r = blockIdx.x;
    if (r >= R_NUM) return;

    int len = glen[r];
    if (len > L_NUM) len = L_NUM;
    if (len < 0) len = 0;

    // Gather + mask: X[i][c] = (i<len) ? emb[gidx[r,i]][c] : 0
#pragma unroll 4
    for (int it = 0; it < (L_NUM * C_NUM) / NT; it++) {
        int idx = tid + it * NT;
        int i = idx >> 9, c = idx & (C_NUM - 1);
        float v = 0.f;
        if (i < len) v = emb[(size_t)gidx[r * L_NUM + i] * C_NUM + c];
        sm->X[i * LD + c] = v;
    }
    __syncthreads();

    // Encoder SABs 0,1 (y_mask & x_mask = len)
    for (int blk = 0; blk < 2; blk++) {
        mab_sab(sm,
                Wq + blk * CC, Wk + blk * CC, Wv + blk * CC, Wo + blk * CC, ffW + blk * CC,
                bq + blk * C_NUM, bk + blk * C_NUM, bv + blk * C_NUM, bo + blk * C_NUM, ffb + blk * C_NUM,
                g1 + blk * C_NUM, b1 + blk * C_NUM, g2 + blk * C_NUM, b2 + blk * C_NUM,
                len, len, tid);
    }

    // y = relu(X @ pW^T + pb); copy back into X
    gemm32(sm->X, pW, pb, sm->A, sm->Wp, tid, true);
#pragma unroll 4
    for (int it = 0; it < (L_NUM * C_NUM) / NT; it++) {
        int idx = tid + it * NT;
        int i = idx >> 9, c = idx & (C_NUM - 1);
        sm->X[i * LD + c] = sm->A[i * LD + c];
    }
    __syncthreads();

    // PMA (block 2): seed (1 query) attends over X with y_mask=len, x_mask=None.
    float* psc = sm->S;            // 128 floats
    float* xs  = sm->S + 512;      // current 1-token state
    float* vq  = sm->S + 1024;     // temp
    float* vt  = sm->S + 1536;     // temp
    for (int c = tid; c < C_NUM; c += NT) xs[c] = seed[c];
    __syncthreads();

    vec_gemm(xs, Wq + 2 * CC, bq + 2 * C_NUM, vq, tid, false);        // q
    gemm32(sm->X, Wk + 2 * CC, bk + 2 * C_NUM, sm->A, sm->Wp, tid, false); // K
    gemm32(sm->X, Wv + 2 * CC, bv + 2 * C_NUM, sm->B, sm->Wp, tid, false); // V
    pma_attn(sm, vq, psc, vt, len, tid);                              // attn out -> vt
    vec_gemm(vt, Wo + 2 * CC, bo + 2 * C_NUM, vq, tid, false);        // O -> vq
    vec_add_ln(xs, vq, g1 + 2 * C_NUM, b1 + 2 * C_NUM, sm->red, tid); // xs = LN(seed + O)
    vec_gemm(xs, ffW + 2 * CC, ffb + 2 * C_NUM, vt, tid, true);       // relu FF -> vt
    vec_add_ln(xs, vt, g2 + 2 * C_NUM, b2 + 2 * C_NUM, sm->red, tid);

    // Decoder SAB (block 3) on one token: softmax over 1 key == 1 -> out == v.
    vec_gemm(xs, Wv + 3 * CC, bv + 3 * C_NUM, vq, tid, false);        // v
    vec_gemm(vq, Wo + 3 * CC, bo + 3 * C_NUM, vt, tid, false);        // O
    vec_add_ln(xs, vt, g1 + 3 * C_NUM, b1 + 3 * C_NUM, sm->red, tid);
    vec_gemm(xs, ffW + 3 * CC, ffb + 3 * C_NUM, vq, tid, true);       // relu FF
    vec_add_ln(xs, vq, g2 + 3 * C_NUM, b2 + 3 * C_NUM, sm->red, tid);

    // out[r] = xs (mean over 1 seed), zeroed if empty reaction
    for (int c = tid; c < C_NUM; c += NT)
        out[(size_t)r * C_NUM + c] = (len > 0) ? xs[c] : 0.f;
}

extern "C" void kernel_launch(void* const* d_in, const int* in_sizes, int n_in,
                              void* d_out, int out_size)
{
    const float* emb  = (const float*)d_in[0];
    const int*   gidx = (const int*)d_in[1];
    const int*   glen = (const int*)d_in[2];
    const float* Wq   = (const float*)d_in[3];
    const float* Wk   = (const float*)d_in[4];
    const float* Wv   = (const float*)d_in[5];
    const float* Wo   = (const float*)d_in[6];
    const float* ffW  = (const float*)d_in[7];
    const float* bq   = (const float*)d_in[8];
    const float* bk   = (const float*)d_in[9];
    const float* bv   = (const float*)d_in[10];
    const float* bo   = (const float*)d_in[11];
    const float* ffb  = (const float*)d_in[12];
    const float* g1   = (const float*)d_in[13];
    const float* b1   = (const float*)d_in[14];
    const float* g2   = (const float*)d_in[15];
    const float* b2   = (const float*)d_in[16];
    const float* pW   = (const float*)d_in[17];
    const float* pb   = (const float*)d_in[18];
    const float* seed = (const float*)d_in[19];

    (void)in_sizes; (void)n_in; (void)out_size;

    cudaFuncSetAttribute(rxn_set_transformer_kernel,
                         cudaFuncAttributeMaxDynamicSharedMemorySize,
                         (int)sizeof(Smem));

    rxn_set_transformer_kernel<<<R_NUM, NT, sizeof(Smem)>>>(
        emb, gidx, glen, Wq, Wk, Wv, Wo, ffW,
        bq, bk, bv, bo, ffb, g1, b1, g2, b2,
        pW, pb, seed, (float*)d_out);
}

// round 10
// speedup vs baseline: 2.2834x; 2.2834x over previous
#include <cuda_runtime.h>

#define R_NUM 4096
#define L_NUM 32
#define C_NUM 512
#define CC    (C_NUM*C_NUM)
#define H_NUM 4
#define DH    128
#define NT    512
#define LD    516          // smem row stride (floats): conflict-free for frag pattern
#define LN_EPS 1e-5f

typedef unsigned long long u64;

struct Smem {
    float  X[L_NUM * LD];            // 66048 B
    float  A[L_NUM * LD];
    float  B[L_NUM * LD];
    float  S[H_NUM * L_NUM * L_NUM]; // 16384 B, overlaid with PMA vectors after SABs
    float  red[40];
};

__device__ __forceinline__ void ffma2(u64& d, u64 a, u64 b) {
    asm("fma.rn.f32x2 %0, %1, %2, %0;" : "+l"(d) : "l"(a), "l"(b));
}
__device__ __forceinline__ float hadd2(u64 v) {
    return __uint_as_float((unsigned)v) + __uint_as_float((unsigned)(v >> 32));
}
__device__ __forceinline__ float warp_sum(float v) {
#pragma unroll
    for (int o = 16; o; o >>= 1) v += __shfl_xor_sync(0xffffffffu, v, o);
    return v;
}
__device__ __forceinline__ unsigned cvt_tf32(float x) {
    unsigned r; asm("cvt.rna.tf32.f32 %0, %1;" : "=r"(r) : "f"(x)); return r;
}
__device__ __forceinline__ void mma_tf32(float* d, const unsigned* a, const unsigned* b) {
    asm("mma.sync.aligned.m16n8k8.row.col.f32.tf32.tf32.f32 "
        "{%0,%1,%2,%3}, {%4,%5,%6,%7}, {%8,%9}, {%0,%1,%2,%3};"
        : "+f"(d[0]), "+f"(d[1]), "+f"(d[2]), "+f"(d[3])
        : "r"(a[0]), "r"(a[1]), "r"(a[2]), "r"(a[3]), "r"(b[0]), "r"(b[1]));
}

// Out[32][512] = Xs[32][512] @ Wg[512,512]^T + bg  (tf32 tensor-core path).
// 16 warps; warp w owns cols [w*32, w*32+32), all 32 rows.
// A frags from smem (Xs), B frags straight from global W (L2/L1 resident),
// register double-buffered across k8 steps; no block barriers in the K loop.
__device__ __noinline__ void gemm32(const float* __restrict__ Xs, const float* __restrict__ Wg,
                                    const float* __restrict__ bg, float* __restrict__ Out,
                                    int tid, bool relu)
{
    const int w = tid >> 5, lane = tid & 31;
    const int gid = lane >> 2, tig = lane & 3;
    const int n0 = w * 32;

    float d[2][4][4];
#pragma unroll
    for (int mf = 0; mf < 2; mf++)
#pragma unroll
        for (int nf = 0; nf < 4; nf++)
#pragma unroll
            for (int q = 0; q < 4; q++) d[mf][nf][q] = 0.f;

    // raw fp32 operand buffers (double-buffered); cvt at consume time
    float af[2][8], bf[2][8];

    // per-thread base pointers
    const float* xb0 = Xs + gid * LD + tig;              // mf=0 rows
    const float* wb[4];
#pragma unroll
    for (int nf = 0; nf < 4; nf++)
        wb[nf] = Wg + (size_t)(n0 + nf * 8 + gid) * C_NUM + tig;

    // prefetch k0 = 0
#pragma unroll
    for (int mf = 0; mf < 2; mf++) {
        const float* xb = xb0 + mf * 16 * LD;
        af[0][mf * 4 + 0] = xb[0];
        af[0][mf * 4 + 1] = xb[8 * LD];
        af[0][mf * 4 + 2] = xb[4];
        af[0][mf * 4 + 3] = xb[8 * LD + 4];
    }
#pragma unroll
    for (int nf = 0; nf < 4; nf++) {
        bf[0][nf * 2 + 0] = wb[nf][0];
        bf[0][nf * 2 + 1] = wb[nf][4];
    }

#pragma unroll 4
    for (int k0 = 0; k0 < C_NUM; k0 += 8) {
        const int p = (k0 >> 3) & 1;
        if (k0 + 8 < C_NUM) {
            const int kn = k0 + 8;
#pragma unroll
            for (int mf = 0; mf < 2; mf++) {
                const float* xb = xb0 + mf * 16 * LD + kn;
                af[p ^ 1][mf * 4 + 0] = xb[0];
                af[p ^ 1][mf * 4 + 1] = xb[8 * LD];
                af[p ^ 1][mf * 4 + 2] = xb[4];
                af[p ^ 1][mf * 4 + 3] = xb[8 * LD + 4];
            }
#pragma unroll
            for (int nf = 0; nf < 4; nf++) {
                bf[p ^ 1][nf * 2 + 0] = wb[nf][kn];
                bf[p ^ 1][nf * 2 + 1] = wb[nf][kn + 4];
            }
        }
        unsigned at[8], bt[8];
#pragma unroll
        for (int q = 0; q < 8; q++) at[q] = cvt_tf32(af[p][q]);
#pragma unroll
        for (int q = 0; q < 8; q++) bt[q] = cvt_tf32(bf[p][q]);
#pragma unroll
        for (int mf = 0; mf < 2; mf++)
#pragma unroll
            for (int nf = 0; nf < 4; nf++)
                mma_tf32(d[mf][nf], at + mf * 4, bt + nf * 2);
    }

    // epilogue: D(gid,2tig)/(gid,2tig+1)/(gid+8,..) per frag; add bias, optional relu
#pragma unroll
    for (int mf = 0; mf < 2; mf++)
#pragma unroll
        for (int nf = 0; nf < 4; nf++) {
            int col = n0 + nf * 8 + 2 * tig;
            float bb0 = bg[col], bb1 = bg[col + 1];
            int r0 = mf * 16 + gid, r1 = r0 + 8;
            float v00 = d[mf][nf][0] + bb0, v01 = d[mf][nf][1] + bb1;
            float v10 = d[mf][nf][2] + bb0, v11 = d[mf][nf][3] + bb1;
            if (relu) {
                v00 = fmaxf(v00, 0.f); v01 = fmaxf(v01, 0.f);
                v10 = fmaxf(v10, 0.f); v11 = fmaxf(v11, 0.f);
            }
            *reinterpret_cast<float2*>(Out + r0 * LD + col) = make_float2(v00, v01);
            *reinterpret_cast<float2*>(Out + r1 * LD + col) = make_float2(v10, v11);
        }
    __syncthreads();
}

// scores[h][i][j] = dot(Q[i,h*128:],K[j,:])/sqrt(128); mask j>=ylen; softmax over j.
__device__ __noinline__ void sab_scores_softmax(const float* __restrict__ Q, const float* __restrict__ K,
                                                float* __restrict__ S, int ylen, int tid)
{
    const float scale = 0.08838834764831845f;  // 1/sqrt(128)
#pragma unroll
    for (int it = 0; it < 8; it++) {
        int idx = tid + it * NT;               // h*1024 + i*32 + j
        int h = idx >> 10, i = (idx >> 5) & 31, j = idx & 31;
        const ulonglong2* q2 = reinterpret_cast<const ulonglong2*>(Q + i * LD + h * DH);
        const ulonglong2* k2 = reinterpret_cast<const ulonglong2*>(K + j * LD + h * DH);
        u64 a0 = 0ull, a1 = 0ull;
#pragma unroll
        for (int d = 0; d < DH / 4; d++) {
            ulonglong2 qa = q2[d], kb = k2[d];
            ffma2(a0, qa.x, kb.x);
            ffma2(a1, qa.y, kb.y);
        }
        S[idx] = (hadd2(a0) + hadd2(a1)) * scale;
    }
    __syncthreads();
    if (tid < H_NUM * L_NUM) {
        float* row = S + tid * L_NUM;          // tid = h*32 + i
        float mx = -1e30f;
        for (int j = 0; j < ylen; j++) mx = fmaxf(mx, row[j]);
        float sum = 0.f;
        for (int j = 0; j < L_NUM; j++) {
            float e = (j < ylen) ? __expf(row[j] - mx) : 0.f;
            row[j] = e; sum += e;
        }
        float inv = 1.f / sum;
        for (int j = 0; j < L_NUM; j++) row[j] *= inv;
    }
    __syncthreads();
}

// Out[i][c] = sum_j S[h(c)][i][j] * V[j][c]
__device__ __noinline__ void attn_v(const float* __restrict__ S, const float* __restrict__ V,
                                    float* __restrict__ Out, int ylen, int tid)
{
    const int rg = tid >> 7, cg = tid & 127;
    float acc[8][4];
#pragma unroll
    for (int a = 0; a < 8; a++)
#pragma unroll
        for (int b = 0; b < 4; b++) acc[a][b] = 0.f;

    for (int jk = 0; jk < ylen; jk++) {
        float vv[4];
#pragma unroll
        for (int jj = 0; jj < 4; jj++) vv[jj] = V[jk * LD + cg + 128 * jj];
        float sv[H_NUM][8];
#pragma unroll
        for (int h = 0; h < H_NUM; h++)
#pragma unroll
            for (int ii = 0; ii < 8; ii++)
                sv[h][ii] = S[h * (L_NUM * L_NUM) + (rg * 8 + ii) * L_NUM + jk];
#pragma unroll
        for (int jj = 0; jj < 4; jj++) {       // h = (cg+128*jj)>>7 == jj (cg<128)
#pragma unroll
            for (int ii = 0; ii < 8; ii++)
                acc[ii][jj] = fmaf(sv[jj][ii], vv[jj], acc[ii][jj]);
        }
    }
#pragma unroll
    for (int jj = 0; jj < 4; jj++)
#pragma unroll
        for (int ii = 0; ii < 8; ii++)
            Out[(rg * 8 + ii) * LD + cg + 128 * jj] = acc[ii][jj];
    __syncthreads();
}

// X[i] = LN(X[i] + (i<xm ? Y[i] : 0)) rowwise with gamma/beta
__device__ __noinline__ void sab_add_ln(float* __restrict__ X, const float* __restrict__ Y,
                                        const float* __restrict__ g, const float* __restrict__ b,
                                        int xm, int tid)
{
    const int w = tid >> 5, lane = tid & 31;
    for (int row = w; row < L_NUM; row += 16) {
        const float* yr = Y + row * LD;
        float* xr = X + row * LD;
        bool useY = row < xm;
        float s = 0.f, s2 = 0.f;
        for (int c = lane; c < C_NUM; c += 32) {
            float v = xr[c] + (useY ? yr[c] : 0.f);
            s += v; s2 += v * v;
        }
        s = warp_sum(s); s2 = warp_sum(s2);
        float mean = s * (1.f / C_NUM);
        float var = s2 * (1.f / C_NUM) - mean * mean;
        float rstd = rsqrtf(var + LN_EPS);
        for (int c = lane; c < C_NUM; c += 32) {
            float v = xr[c] + (useY ? yr[c] : 0.f);
            xr[c] = (v - mean) * rstd * g[c] + b[c];
        }
    }
    __syncthreads();
}

__device__ __noinline__ void mab_sab(Smem* sm,
    const float* Wq, const float* Wk, const float* Wv, const float* Wo, const float* ffW,
    const float* bq, const float* bk, const float* bv, const float* bo, const float* ffb,
    const float* g1, const float* b1, const float* g2, const float* b2,
    int ylen, int xm, int tid)
{
    gemm32(sm->X, Wq, bq, sm->A, tid, false);             // Q -> A
    gemm32(sm->X, Wk, bk, sm->B, tid, false);             // K -> B
    sab_scores_softmax(sm->A, sm->B, sm->S, ylen, tid);   // attn -> S
    gemm32(sm->X, Wv, bv, sm->B, tid, false);             // V -> B (K dead)
    attn_v(sm->S, sm->B, sm->A, ylen, tid);               // attn@V -> A (Q dead)
    gemm32(sm->A, Wo, bo, sm->B, tid, false);             // O -> B
    sab_add_ln(sm->X, sm->B, g1, b1, xm, tid);            // X = LN(X + mask(O))
    gemm32(sm->X, ffW, ffb, sm->A, tid, true);            // relu FF -> A
    sab_add_ln(sm->X, sm->A, g2, b2, L_NUM, tid);         // X = LN(X + FF)
}

// out[j] = sum_k xin[k]*Wg[j][k] + bg[j]   (xin: smem [512]); one j per thread
__device__ __noinline__ void vec_gemm(const float* __restrict__ xin, const float* __restrict__ Wg,
                                      const float* __restrict__ bg, float* __restrict__ out,
                                      int tid, bool relu)
{
    const ulonglong2* x2 = reinterpret_cast<const ulonglong2*>(xin);
    int j = tid;                               // NT == C_NUM
    const ulonglong2* w2 = reinterpret_cast<const ulonglong2*>(Wg + (size_t)j * C_NUM);
    u64 a0 = 0ull, a1 = 0ull;
#pragma unroll 8
    for (int d = 0; d < C_NUM / 4; d++) {
        ulonglong2 w = w2[d], x = x2[d];
        ffma2(a0, w.x, x.x);
        ffma2(a1, w.y, x.y);
    }
    float v = hadd2(a0) + hadd2(a1) + bg[j];
    if (relu) v = fmaxf(v, 0.f);
    out[j] = v;
    __syncthreads();
}

// x = LN(x + y) over a single 512-vector (block-wide, 16 warps)
__device__ __noinline__ void vec_add_ln(float* __restrict__ x, const float* __restrict__ y,
                                        const float* __restrict__ g, const float* __restrict__ b,
                                        float* __restrict__ red, int tid)
{
    float s = 0.f, s2 = 0.f;
    for (int c = tid; c < C_NUM; c += NT) {
        float v = x[c] + y[c]; s += v; s2 += v * v;
    }
    s = warp_sum(s); s2 = warp_sum(s2);
    int w = tid >> 5, lane = tid & 31;
    if (lane == 0) { red[w] = s; red[16 + w] = s2; }
    __syncthreads();
    if (tid == 0) {
        float ts = 0, ts2 = 0;
        for (int i = 0; i < 16; i++) { ts += red[i]; ts2 += red[16 + i]; }
        float mean = ts * (1.f / C_NUM);
        float var = ts2 * (1.f / C_NUM) - mean * mean;
        red[32] = mean; red[33] = rsqrtf(var + LN_EPS);
    }
    __syncthreads();
    float mean = red[32], rstd = red[33];
    for (int c = tid; c < C_NUM; c += NT) {
        float v = x[c] + y[c];
        x[c] = (v - mean) * rstd * g[c] + b[c];
    }
    __syncthreads();
}

// PMA attention: q (smem [512]) over K=sm->A [32,512], V=sm->B; out -> outv [512]
__device__ __noinline__ void pma_attn(Smem* sm, const float* __restrict__ q,
                                      float* __restrict__ psc, float* __restrict__ outv,
                                      int ylen, int tid)
{
    const float scale = 0.08838834764831845f;
    if (tid < H_NUM * L_NUM) {
        int h = tid >> 5, j = tid & 31;
        if (j < ylen) {
            const ulonglong2* q2 = reinterpret_cast<const ulonglong2*>(q + h * DH);
            const ulonglong2* k2 = reinterpret_cast<const ulonglong2*>(sm->A + j * LD + h * DH);
            u64 a0 = 0ull, a1 = 0ull;
#pragma unroll
            for (int d = 0; d < DH / 4; d++) {
                ulonglong2 qa = q2[d], kb = k2[d];
                ffma2(a0, qa.x, kb.x);
                ffma2(a1, qa.y, kb.y);
            }
            psc[h * L_NUM + j] = (hadd2(a0) + hadd2(a1)) * scale;
        }
    }
    __syncthreads();
    if (tid < H_NUM) {
        float* row = psc + tid * L_NUM;
        float mx = -1e30f;
        for (int j = 0; j < ylen; j++) mx = fmaxf(mx, row[j]);
        float sum = 0.f;
        for (int j = 0; j < ylen; j++) { float e = __expf(row[j] - mx); row[j] = e; sum += e; }
        float inv = 1.f / sum;
        for (int j = 0; j < ylen; j++) row[j] *= inv;
    }
    __syncthreads();
    for (int c = tid; c < C_NUM; c += NT) {
        int h = c >> 7;
        float s = 0.f;
        for (int j = 0; j < ylen; j++) s = fmaf(psc[h * L_NUM + j], sm->B[j * LD + c], s);
        outv[c] = s;
    }
    __syncthreads();
}

__global__ void __launch_bounds__(NT, 1)
rxn_set_transformer_kernel(
    const float* __restrict__ emb, const int* __restrict__ gidx, const int* __restrict__ glen,
    const float* __restrict__ Wq, const float* __restrict__ Wk, const float* __restrict__ Wv,
    const float* __restrict__ Wo, const float* __restrict__ ffW,
    const float* __restrict__ bq, const float* __restrict__ bk, const float* __restrict__ bv,
    const float* __restrict__ bo, const float* __restrict__ ffb,
    const float* __restrict__ g1, const float* __restrict__ b1,
    const float* __restrict__ g2, const float* __restrict__ b2,
    const float* __restrict__ pW, const float* __restrict__ pb,
    const float* __restrict__ seed, float* __restrict__ out)
{
    extern __shared__ char smem_raw[];
    Smem* sm = reinterpret_cast<Smem*>(smem_raw);
    const int tid = threadIdx.x;
    const int r = blockIdx.x;
    if (r >= R_NUM) return;

    int len = glen[r];
    if (len > L_NUM) len = L_NUM;
    if (len < 0) len = 0;

    // Gather + mask: X[i][c] = (i<len) ? emb[gidx[r,i]][c] : 0
#pragma unroll 4
    for (int it = 0; it < (L_NUM * C_NUM) / NT; it++) {
        int idx = tid + it * NT;
        int i = idx >> 9, c = idx & (C_NUM - 1);
        float v = 0.f;
        if (i < len) v = emb[(size_t)gidx[r * L_NUM + i] * C_NUM + c];
        sm->X[i * LD + c] = v;
    }
    __syncthreads();

    // Encoder SABs 0,1 (y_mask & x_mask = len)
    for (int blk = 0; blk < 2; blk++) {
        mab_sab(sm,
                Wq + blk * CC, Wk + blk * CC, Wv + blk * CC, Wo + blk * CC, ffW + blk * CC,
                bq + blk * C_NUM, bk + blk * C_NUM, bv + blk * C_NUM, bo + blk * C_NUM, ffb + blk * C_NUM,
                g1 + blk * C_NUM, b1 + blk * C_NUM, g2 + blk * C_NUM, b2 + blk * C_NUM,
                len, len, tid);
    }

    // y = relu(X @ pW^T + pb); copy back into X
    gemm32(sm->X, pW, pb, sm->A, tid, true);
#pragma unroll 4
    for (int it = 0; it < (L_NUM * C_NUM) / NT; it++) {
        int idx = tid + it * NT;
        int i = idx >> 9, c = idx & (C_NUM - 1);
        sm->X[i * LD + c] = sm->A[i * LD + c];
    }
    __syncthreads();

    // PMA (block 2): seed (1 query) attends over X with y_mask=len, x_mask=None.
    float* psc = sm->S;            // 128 floats
    float* xs  = sm->S + 512;      // current 1-token state
    float* vq  = sm->S + 1024;     // temp
    float* vt  = sm->S + 1536;     // temp
    for (int c = tid; c < C_NUM; c += NT) xs[c] = seed[c];
    __syncthreads();

    vec_gemm(xs, Wq + 2 * CC, bq + 2 * C_NUM, vq, tid, false);        // q
    gemm32(sm->X, Wk + 2 * CC, bk + 2 * C_NUM, sm->A, tid, false);    // K
    gemm32(sm->X, Wv + 2 * CC, bv + 2 * C_NUM, sm->B, tid, false);    // V
    pma_attn(sm, vq, psc, vt, len, tid);                              // attn out -> vt
    vec_gemm(vt, Wo + 2 * CC, bo + 2 * C_NUM, vq, tid, false);        // O -> vq
    vec_add_ln(xs, vq, g1 + 2 * C_NUM, b1 + 2 * C_NUM, sm->red, tid); // xs = LN(seed + O)
    vec_gemm(xs, ffW + 2 * CC, ffb + 2 * C_NUM, vt, tid, true);       // relu FF -> vt
    vec_add_ln(xs, vt, g2 + 2 * C_NUM, b2 + 2 * C_NUM, sm->red, tid);

    // Decoder SAB (block 3) on one token: softmax over 1 key == 1 -> out == v.
    vec_gemm(xs, Wv + 3 * CC, bv + 3 * C_NUM, vq, tid, false);        // v
    vec_gemm(vq, Wo + 3 * CC, bo + 3 * C_NUM, vt, tid, false);        // O
    vec_add_ln(xs, vt, g1 + 3 * C_NUM, b1 + 3 * C_NUM, sm->red, tid);
    vec_gemm(xs, ffW + 3 * CC, ffb + 3 * C_NUM, vq, tid, true);       // relu FF
    vec_add_ln(xs, vq, g2 + 3 * C_NUM, b2 + 3 * C_NUM, sm->red, tid);

    // out[r] = xs (mean over 1 seed), zeroed if empty reaction
    for (int c = tid; c < C_NUM; c += NT)
        out[(size_t)r * C_NUM + c] = (len > 0) ? xs[c] : 0.f;
}

extern "C" void kernel_launch(void* const* d_in, const int* in_sizes, int n_in,
                              void* d_out, int out_size)
{
    const float* emb  = (const float*)d_in[0];
    const int*   gidx = (const int*)d_in[1];
    const int*   glen = (const int*)d_in[2];
    const float* Wq   = (const float*)d_in[3];
    const float* Wk   = (const float*)d_in[4];
    const float* Wv   = (const float*)d_in[5];
    const float* Wo   = (const float*)d_in[6];
    const float* ffW  = (const float*)d_in[7];
    const float* bq   = (const float*)d_in[8];
    const float* bk   = (const float*)d_in[9];
    const float* bv   = (const float*)d_in[10];
    const float* bo   = (const float*)d_in[11];
    const float* ffb  = (const float*)d_in[12];
    const float* g1   = (const float*)d_in[13];
    const float* b1   = (const float*)d_in[14];
    const float* g2   = (const float*)d_in[15];
    const float* b2   = (const float*)d_in[16];
    const float* pW   = (const float*)d_in[17];
    const float* pb   = (const float*)d_in[18];
    const float* seed = (const float*)d_in[19];

    (void)in_sizes; (void)n_in; (void)out_size;

    cudaFuncSetAttribute(rxn_set_transformer_kernel,
                         cudaFuncAttributeMaxDynamicSharedMemorySize,
                         (int)sizeof(Smem));

    rxn_set_transformer_kernel<<<R_NUM, NT, sizeof(Smem)>>>(
        emb, gidx, glen, Wq, Wk, Wv, Wo, ffW,
        bq, bk, bv, bo, ffb, g1, b1, g2, b2,
        pW, pb, seed, (float*)d_out);
}

// round 11
// speedup vs baseline: 2.2864x; 1.0013x over previous
#include <cuda_runtime.h>

#define R_NUM 4096
#define L_NUM 32
#define C_NUM 512
#define CC    (C_NUM*C_NUM)
#define H_NUM 4
#define DH    128
#define NT    512
#define LD    516          // smem row stride (floats): conflict-free for frag pattern
#define LN_EPS 1e-5f

typedef unsigned long long u64;

struct Smem {
    float  X[L_NUM * LD];            // 66048 B
    float  A[L_NUM * LD];
    float  B[L_NUM * LD];
    float  S[H_NUM * L_NUM * L_NUM]; // 16384 B, overlaid with PMA vectors after SABs
    float  red[40];
};

__device__ __forceinline__ void ffma2(u64& d, u64 a, u64 b) {
    asm("fma.rn.f32x2 %0, %1, %2, %0;" : "+l"(d) : "l"(a), "l"(b));
}
__device__ __forceinline__ float hadd2(u64 v) {
    return __uint_as_float((unsigned)v) + __uint_as_float((unsigned)(v >> 32));
}
__device__ __forceinline__ float warp_sum(float v) {
#pragma unroll
    for (int o = 16; o; o >>= 1) v += __shfl_xor_sync(0xffffffffu, v, o);
    return v;
}
__device__ __forceinline__ unsigned cvt_tf32(float x) {
    unsigned r; asm("cvt.rna.tf32.f32 %0, %1;" : "=r"(r) : "f"(x)); return r;
}
__device__ __forceinline__ void mma_tf32(float* d, const unsigned* a, const unsigned* b) {
    asm("mma.sync.aligned.m16n8k8.row.col.f32.tf32.tf32.f32 "
        "{%0,%1,%2,%3}, {%4,%5,%6,%7}, {%8,%9}, {%0,%1,%2,%3};"
        : "+f"(d[0]), "+f"(d[1]), "+f"(d[2]), "+f"(d[3])
        : "r"(a[0]), "r"(a[1]), "r"(a[2]), "r"(a[3]), "r"(b[0]), "r"(b[1]));
}

// Out[32][512] = Xs[32][512] @ Wg[512,512]^T + bg  (tf32 tensor-core path).
// 16 warps; warp w owns cols [w*32, w*32+32), all 32 rows.
// A frags from smem (Xs), B frags straight from global W (L2/L1 resident),
// register double-buffered across k8 steps; no block barriers in the K loop.
__device__ __noinline__ void gemm32(const float* __restrict__ Xs, const float* __restrict__ Wg,
                                    const float* __restrict__ bg, float* __restrict__ Out,
                                    int tid, bool relu)
{
    const int w = tid >> 5, lane = tid & 31;
    const int gid = lane >> 2, tig = lane & 3;
    const int n0 = w * 32;

    float d[2][4][4];
#pragma unroll
    for (int mf = 0; mf < 2; mf++)
#pragma unroll
        for (int nf = 0; nf < 4; nf++)
#pragma unroll
            for (int q = 0; q < 4; q++) d[mf][nf][q] = 0.f;

    // raw fp32 operand buffers (double-buffered); cvt at consume time
    float af[2][8], bf[2][8];

    // per-thread base pointers
    const float* xb0 = Xs + gid * LD + tig;              // mf=0 rows
    const float* wb[4];
#pragma unroll
    for (int nf = 0; nf < 4; nf++)
        wb[nf] = Wg + (size_t)(n0 + nf * 8 + gid) * C_NUM + tig;

    // prefetch k0 = 0
#pragma unroll
    for (int mf = 0; mf < 2; mf++) {
        const float* xb = xb0 + mf * 16 * LD;
        af[0][mf * 4 + 0] = xb[0];
        af[0][mf * 4 + 1] = xb[8 * LD];
        af[0][mf * 4 + 2] = xb[4];
        af[0][mf * 4 + 3] = xb[8 * LD + 4];
    }
#pragma unroll
    for (int nf = 0; nf < 4; nf++) {
        bf[0][nf * 2 + 0] = wb[nf][0];
        bf[0][nf * 2 + 1] = wb[nf][4];
    }

#pragma unroll 4
    for (int k0 = 0; k0 < C_NUM; k0 += 8) {
        const int p = (k0 >> 3) & 1;
        if (k0 + 8 < C_NUM) {
            const int kn = k0 + 8;
#pragma unroll
            for (int mf = 0; mf < 2; mf++) {
                const float* xb = xb0 + mf * 16 * LD + kn;
                af[p ^ 1][mf * 4 + 0] = xb[0];
                af[p ^ 1][mf * 4 + 1] = xb[8 * LD];
                af[p ^ 1][mf * 4 + 2] = xb[4];
                af[p ^ 1][mf * 4 + 3] = xb[8 * LD + 4];
            }
#pragma unroll
            for (int nf = 0; nf < 4; nf++) {
                bf[p ^ 1][nf * 2 + 0] = wb[nf][kn];
                bf[p ^ 1][nf * 2 + 1] = wb[nf][kn + 4];
            }
        }
        unsigned at[8], bt[8];
#pragma unroll
        for (int q = 0; q < 8; q++) at[q] = cvt_tf32(af[p][q]);
#pragma unroll
        for (int q = 0; q < 8; q++) bt[q] = cvt_tf32(bf[p][q]);
#pragma unroll
        for (int mf = 0; mf < 2; mf++)
#pragma unroll
            for (int nf = 0; nf < 4; nf++)
                mma_tf32(d[mf][nf], at + mf * 4, bt + nf * 2);
    }

    // epilogue: D(gid,2tig)/(gid,2tig+1)/(gid+8,..) per frag; add bias, optional relu
#pragma unroll
    for (int mf = 0; mf < 2; mf++)
#pragma unroll
        for (int nf = 0; nf < 4; nf++) {
            int col = n0 + nf * 8 + 2 * tig;
            float bb0 = bg[col], bb1 = bg[col + 1];
            int r0 = mf * 16 + gid, r1 = r0 + 8;
            float v00 = d[mf][nf][0] + bb0, v01 = d[mf][nf][1] + bb1;
            float v10 = d[mf][nf][2] + bb0, v11 = d[mf][nf][3] + bb1;
            if (relu) {
                v00 = fmaxf(v00, 0.f); v01 = fmaxf(v01, 0.f);
                v10 = fmaxf(v10, 0.f); v11 = fmaxf(v11, 0.f);
            }
            *reinterpret_cast<float2*>(Out + r0 * LD + col) = make_float2(v00, v01);
            *reinterpret_cast<float2*>(Out + r1 * LD + col) = make_float2(v10, v11);
        }
    __syncthreads();
}

// scores[h][i][j] = dot(Q[i,h*128:],K[j,:])/sqrt(128); mask j>=ylen; softmax over j.
__device__ __noinline__ void sab_scores_softmax(const float* __restrict__ Q, const float* __restrict__ K,
                                                float* __restrict__ S, int ylen, int tid)
{
    const float scale = 0.08838834764831845f;  // 1/sqrt(128)
#pragma unroll
    for (int it = 0; it < 8; it++) {
        int idx = tid + it * NT;               // h*1024 + i*32 + j
        int h = idx >> 10, i = (idx >> 5) & 31, j = idx & 31;
        const ulonglong2* q2 = reinterpret_cast<const ulonglong2*>(Q + i * LD + h * DH);
        const ulonglong2* k2 = reinterpret_cast<const ulonglong2*>(K + j * LD + h * DH);
        u64 a0 = 0ull, a1 = 0ull;
#pragma unroll
        for (int d = 0; d < DH / 4; d++) {
            ulonglong2 qa = q2[d], kb = k2[d];
            ffma2(a0, qa.x, kb.x);
            ffma2(a1, qa.y, kb.y);
        }
        S[idx] = (hadd2(a0) + hadd2(a1)) * scale;
    }
    __syncthreads();
    if (tid < H_NUM * L_NUM) {
        float* row = S + tid * L_NUM;          // tid = h*32 + i
        float mx = -1e30f;
        for (int j = 0; j < ylen; j++) mx = fmaxf(mx, row[j]);
        float sum = 0.f;
        for (int j = 0; j < L_NUM; j++) {
            float e = (j < ylen) ? __expf(row[j] - mx) : 0.f;
            row[j] = e; sum += e;
        }
        float inv = 1.f / sum;
        for (int j = 0; j < L_NUM; j++) row[j] *= inv;
    }
    __syncthreads();
}

// Out[i][c] = sum_j S[h(c)][i][j] * V[j][c]
__device__ __noinline__ void attn_v(const float* __restrict__ S, const float* __restrict__ V,
                                    float* __restrict__ Out, int ylen, int tid)
{
    const int rg = tid >> 7, cg = tid & 127;
    float acc[8][4];
#pragma unroll
    for (int a = 0; a < 8; a++)
#pragma unroll
        for (int b = 0; b < 4; b++) acc[a][b] = 0.f;

    for (int jk = 0; jk < ylen; jk++) {
        float vv[4];
#pragma unroll
        for (int jj = 0; jj < 4; jj++) vv[jj] = V[jk * LD + cg + 128 * jj];
        float sv[H_NUM][8];
#pragma unroll
        for (int h = 0; h < H_NUM; h++)
#pragma unroll
            for (int ii = 0; ii < 8; ii++)
                sv[h][ii] = S[h * (L_NUM * L_NUM) + (rg * 8 + ii) * L_NUM + jk];
#pragma unroll
        for (int jj = 0; jj < 4; jj++) {       // h = (cg+128*jj)>>7 == jj (cg<128)
#pragma unroll
            for (int ii = 0; ii < 8; ii++)
                acc[ii][jj] = fmaf(sv[jj][ii], vv[jj], acc[ii][jj]);
        }
    }
#pragma unroll
    for (int jj = 0; jj < 4; jj++)
#pragma unroll
        for (int ii = 0; ii < 8; ii++)
            Out[(rg * 8 + ii) * LD + cg + 128 * jj] = acc[ii][jj];
    __syncthreads();
}

// X[i] = LN(X[i] + (i<xm ? Y[i] : 0)) rowwise with gamma/beta
__device__ __noinline__ void sab_add_ln(float* __restrict__ X, const float* __restrict__ Y,
                                        const float* __restrict__ g, const float* __restrict__ b,
                                        int xm, int tid)
{
    const int w = tid >> 5, lane = tid & 31;
    for (int row = w; row < L_NUM; row += 16) {
        const float* yr = Y + row * LD;
        float* xr = X + row * LD;
        bool useY = row < xm;
        float s = 0.f, s2 = 0.f;
        for (int c = lane; c < C_NUM; c += 32) {
            float v = xr[c] + (useY ? yr[c] : 0.f);
            s += v; s2 += v * v;
        }
        s = warp_sum(s); s2 = warp_sum(s2);
        float mean = s * (1.f / C_NUM);
        float var = s2 * (1.f / C_NUM) - mean * mean;
        float rstd = rsqrtf(var + LN_EPS);
        for (int c = lane; c < C_NUM; c += 32) {
            float v = xr[c] + (useY ? yr[c] : 0.f);
            xr[c] = (v - mean) * rstd * g[c] + b[c];
        }
    }
    __syncthreads();
}

__device__ __noinline__ void mab_sab(Smem* sm,
    const float* Wq, const float* Wk, const float* Wv, const float* Wo, const float* ffW,
    const float* bq, const float* bk, const float* bv, const float* bo, const float* ffb,
    const float* g1, const float* b1, const float* g2, const float* b2,
    int ylen, int xm, int tid)
{
    gemm32(sm->X, Wq, bq, sm->A, tid, false);             // Q -> A
    gemm32(sm->X, Wk, bk, sm->B, tid, false);             // K -> B
    sab_scores_softmax(sm->A, sm->B, sm->S, ylen, tid);   // attn -> S
    gemm32(sm->X, Wv, bv, sm->B, tid, false);             // V -> B (K dead)
    attn_v(sm->S, sm->B, sm->A, ylen, tid);               // attn@V -> A (Q dead)
    gemm32(sm->A, Wo, bo, sm->B, tid, false);             // O -> B
    sab_add_ln(sm->X, sm->B, g1, b1, xm, tid);            // X = LN(X + mask(O))
    gemm32(sm->X, ffW, ffb, sm->A, tid, true);            // relu FF -> A
    sab_add_ln(sm->X, sm->A, g2, b2, L_NUM, tid);         // X = LN(X + FF)
}

// out[j] = sum_k xin[k]*Wg[j][k] + bg[j]   (xin: smem [512]); one j per thread
__device__ __noinline__ void vec_gemm(const float* __restrict__ xin, const float* __restrict__ Wg,
                                      const float* __restrict__ bg, float* __restrict__ out,
                                      int tid, bool relu)
{
    const ulonglong2* x2 = reinterpret_cast<const ulonglong2*>(xin);
    int j = tid;                               // NT == C_NUM
    const ulonglong2* w2 = reinterpret_cast<const ulonglong2*>(Wg + (size_t)j * C_NUM);
    u64 a0 = 0ull, a1 = 0ull;
#pragma unroll 8
    for (int d = 0; d < C_NUM / 4; d++) {
        ulonglong2 w = w2[d], x = x2[d];
        ffma2(a0, w.x, x.x);
        ffma2(a1, w.y, x.y);
    }
    float v = hadd2(a0) + hadd2(a1) + bg[j];
    if (relu) v = fmaxf(v, 0.f);
    out[j] = v;
    __syncthreads();
}

// x = LN(x + y) over a single 512-vector (block-wide, 16 warps)
__device__ __noinline__ void vec_add_ln(float* __restrict__ x, const float* __restrict__ y,
                                        const float* __restrict__ g, const float* __restrict__ b,
                                        float* __restrict__ red, int tid)
{
    float s = 0.f, s2 = 0.f;
    for (int c = tid; c < C_NUM; c += NT) {
        float v = x[c] + y[c]; s += v; s2 += v * v;
    }
    s = warp_sum(s); s2 = warp_sum(s2);
    int w = tid >> 5, lane = tid & 31;
    if (lane == 0) { red[w] = s; red[16 + w] = s2; }
    __syncthreads();
    if (tid == 0) {
        float ts = 0, ts2 = 0;
        for (int i = 0; i < 16; i++) { ts += red[i]; ts2 += red[16 + i]; }
        float mean = ts * (1.f / C_NUM);
        float var = ts2 * (1.f / C_NUM) - mean * mean;
        red[32] = mean; red[33] = rsqrtf(var + LN_EPS);
    }
    __syncthreads();
    float mean = red[32], rstd = red[33];
    for (int c = tid; c < C_NUM; c += NT) {
        float v = x[c] + y[c];
        x[c] = (v - mean) * rstd * g[c] + b[c];
    }
    __syncthreads();
}

// PMA attention: q (smem [512]) over K=sm->A [32,512], V=sm->B; out -> outv [512]
__device__ __noinline__ void pma_attn(Smem* sm, const float* __restrict__ q,
                                      float* __restrict__ psc, float* __restrict__ outv,
                                      int ylen, int tid)
{
    const float scale = 0.08838834764831845f;
    if (tid < H_NUM * L_NUM) {
        int h = tid >> 5, j = tid & 31;
        if (j < ylen) {
            const ulonglong2* q2 = reinterpret_cast<const ulonglong2*>(q + h * DH);
            const ulonglong2* k2 = reinterpret_cast<const ulonglong2*>(sm->A + j * LD + h * DH);
            u64 a0 = 0ull, a1 = 0ull;
#pragma unroll
            for (int d = 0; d < DH / 4; d++) {
                ulonglong2 qa = q2[d], kb = k2[d];
                ffma2(a0, qa.x, kb.x);
                ffma2(a1, qa.y, kb.y);
            }
            psc[h * L_NUM + j] = (hadd2(a0) + hadd2(a1)) * scale;
        }
    }
    __syncthreads();
    if (tid < H_NUM) {
        float* row = psc + tid * L_NUM;
        float mx = -1e30f;
        for (int j = 0; j < ylen; j++) mx = fmaxf(mx, row[j]);
        float sum = 0.f;
        for (int j = 0; j < ylen; j++) { float e = __expf(row[j] - mx); row[j] = e; sum += e; }
        float inv = 1.f / sum;
        for (int j = 0; j < ylen; j++) row[j] *= inv;
    }
    __syncthreads();
    for (int c = tid; c < C_NUM; c += NT) {
        int h = c >> 7;
        float s = 0.f;
        for (int j = 0; j < ylen; j++) s = fmaf(psc[h * L_NUM + j], sm->B[j * LD + c], s);
        outv[c] = s;
    }
    __syncthreads();
}

__global__ void __launch_bounds__(NT, 1)
rxn_set_transformer_kernel(
    const float* __restrict__ emb, const int* __restrict__ gidx, const int* __restrict__ glen,
    const float* __restrict__ Wq, const float* __restrict__ Wk, const float* __restrict__ Wv,
    const float* __restrict__ Wo, const float* __restrict__ ffW,
    const float* __restrict__ bq, const float* __restrict__ bk, const float* __restrict__ bv,
    const float* __restrict__ bo, const float* __restrict__ ffb,
    const float* __restrict__ g1, const float* __restrict__ b1,
    const float* __restrict__ g2, const float* __restrict__ b2,
    const float* __restrict__ pW, const float* __restrict__ pb,
    const float* __restrict__ seed, float* __restrict__ out)
{
    extern __shared__ char smem_raw[];
    Smem* sm = reinterpret_cast<Smem*>(smem_raw);
    const int tid = threadIdx.x;
    const int r = blockIdx.x;
    if (r >= R_NUM) return;

    int len = glen[r];
    if (len > L_NUM) len = L_NUM;
    if (len < 0) len = 0;

    // Gather + mask: X[i][c] = (i<len) ? emb[gidx[r,i]][c] : 0
#pragma unroll 4
    for (int it = 0; it < (L_NUM * C_NUM) / NT; it++) {
        int idx = tid + it * NT;
        int i = idx >> 9, c = idx & (C_NUM - 1);
        float v = 0.f;
        if (i < len) v = emb[(size_t)gidx[r * L_NUM + i] * C_NUM + c];
        sm->X[i * LD + c] = v;
    }
    __syncthreads();

    // Encoder SABs 0,1 (y_mask & x_mask = len)
    for (int blk = 0; blk < 2; blk++) {
        mab_sab(sm,
                Wq + blk * CC, Wk + blk * CC, Wv + blk * CC, Wo + blk * CC, ffW + blk * CC,
                bq + blk * C_NUM, bk + blk * C_NUM, bv + blk * C_NUM, bo + blk * C_NUM, ffb + blk * C_NUM,
                g1 + blk * C_NUM, b1 + blk * C_NUM, g2 + blk * C_NUM, b2 + blk * C_NUM,
                len, len, tid);
    }

    // y = relu(X @ pW^T + pb); copy back into X
    gemm32(sm->X, pW, pb, sm->A, tid, true);
#pragma unroll 4
    for (int it = 0; it < (L_NUM * C_NUM) / NT; it++) {
        int idx = tid + it * NT;
        int i = idx >> 9, c = idx & (C_NUM - 1);
        sm->X[i * LD + c] = sm->A[i * LD + c];
    }
    __syncthreads();

    // PMA (block 2): seed (1 query) attends over X with y_mask=len, x_mask=None.
    float* psc = sm->S;            // 128 floats
    float* xs  = sm->S + 512;      // current 1-token state
    float* vq  = sm->S + 1024;     // temp
    float* vt  = sm->S + 1536;     // temp
    for (int c = tid; c < C_NUM; c += NT) xs[c] = seed[c];
    __syncthreads();

    vec_gemm(xs, Wq + 2 * CC, bq + 2 * C_NUM, vq, tid, false);        // q
    gemm32(sm->X, Wk + 2 * CC, bk + 2 * C_NUM, sm->A, tid, false);    // K
    gemm32(sm->X, Wv + 2 * CC, bv + 2 * C_NUM, sm->B, tid, false);    // V
    pma_attn(sm, vq, psc, vt, len, tid);                              // attn out -> vt
    vec_gemm(vt, Wo + 2 * CC, bo + 2 * C_NUM, vq, tid, false);        // O -> vq
    vec_add_ln(xs, vq, g1 + 2 * C_NUM, b1 + 2 * C_NUM, sm->red, tid); // xs = LN(seed + O)
    vec_gemm(xs, ffW + 2 * CC, ffb + 2 * C_NUM, vt, tid, true);       // relu FF -> vt
    vec_add_ln(xs, vt, g2 + 2 * C_NUM, b2 + 2 * C_NUM, sm->red, tid);

    // Decoder SAB (block 3) on one token: softmax over 1 key == 1 -> out == v.
    vec_gemm(xs, Wv + 3 * CC, bv + 3 * C_NUM, vq, tid, false);        // v
    vec_gemm(vq, Wo + 3 * CC, bo + 3 * C_NUM, vt, tid, false);        // O
    vec_add_ln(xs, vt, g1 + 3 * C_NUM, b1 + 3 * C_NUM, sm->red, tid);
    vec_gemm(xs, ffW + 3 * CC, ffb + 3 * C_NUM, vq, tid, true);       // relu FF
    vec_add_ln(xs, vq, g2 + 3 * C_NUM, b2 + 3 * C_NUM, sm->red, tid);

    // out[r] = xs (mean over 1 seed), zeroed if empty reaction
    for (int c = tid; c < C_NUM; c += NT)
        out[(size_t)r * C_NUM + c] = (len > 0) ? xs[c] : 0.f;
}

extern "C" void kernel_launch(void* const* d_in, const int* in_sizes, int n_in,
                              void* d_out, int out_size)
{
    const float* emb  = (const float*)d_in[0];
    const int*   gidx = (const int*)d_in[1];
    const int*   glen = (const int*)d_in[2];
    const float* Wq   = (const float*)d_in[3];
    const float* Wk   = (const float*)d_in[4];
    const float* Wv   = (const float*)d_in[5];
    const float* Wo   = (const float*)d_in[6];
    const float* ffW  = (const float*)d_in[7];
    const float* bq   = (const float*)d_in[8];
    const float* bk   = (const float*)d_in[9];
    const float* bv   = (const float*)d_in[10];
    const float* bo   = (const float*)d_in[11];
    const float* ffb  = (const float*)d_in[12];
    const float* g1   = (const float*)d_in[13];
    const float* b1   = (const float*)d_in[14];
    const float* g2   = (const float*)d_in[15];
    const float* b2   = (const float*)d_in[16];
    const float* pW   = (const float*)d_in[17];
    const float* pb   = (const float*)d_in[18];
    const float* seed = (const float*)d_in[19];

    (void)in_sizes; (void)n_in; (void)out_size;

    cudaFuncSetAttribute(rxn_set_transformer_kernel,
                         cudaFuncAttributeMaxDynamicSharedMemorySize,
                         (int)sizeof(Smem));

    rxn_set_transformer_kernel<<<R_NUM, NT, sizeof(Smem)>>>(
        emb, gidx, glen, Wq, Wk, Wv, Wo, ffW,
        bq, bk, bv, bo, ffb, g1, b1, g2, b2,
        pW, pb, seed, (float*)d_out);
}

// round 12
// speedup vs baseline: 2.2875x; 1.0005x over previous
#include <cuda_runtime.h>

#define R_NUM 4096
#define L_NUM 32
#define C_NUM 512
#define CC    (C_NUM*C_NUM)
#define H_NUM 4
#define DH    128
#define NT    512
#define LD    516          // smem row stride (floats): conflict-free for frag pattern
#define LN_EPS 1e-5f

typedef unsigned long long u64;

struct Smem {
    float  X[L_NUM * LD];            // 66048 B
    float  A[L_NUM * LD];
    float  B[L_NUM * LD];
    float  S[H_NUM * L_NUM * L_NUM]; // 16384 B, overlaid with PMA vectors after SABs
    float  red[40];
};

__device__ __forceinline__ void ffma2(u64& d, u64 a, u64 b) {
    asm("fma.rn.f32x2 %0, %1, %2, %0;" : "+l"(d) : "l"(a), "l"(b));
}
__device__ __forceinline__ float hadd2(u64 v) {
    return __uint_as_float((unsigned)v) + __uint_as_float((unsigned)(v >> 32));
}
__device__ __forceinline__ float warp_sum(float v) {
#pragma unroll
    for (int o = 16; o; o >>= 1) v += __shfl_xor_sync(0xffffffffu, v, o);
    return v;
}
__device__ __forceinline__ unsigned cvt_tf32(float x) {
    unsigned r; asm("cvt.rna.tf32.f32 %0, %1;" : "=r"(r) : "f"(x)); return r;
}
__device__ __forceinline__ void mma_tf32(float* d, const unsigned* a, const unsigned* b) {
    asm("mma.sync.aligned.m16n8k8.row.col.f32.tf32.tf32.f32 "
        "{%0,%1,%2,%3}, {%4,%5,%6,%7}, {%8,%9}, {%0,%1,%2,%3};"
        : "+f"(d[0]), "+f"(d[1]), "+f"(d[2]), "+f"(d[3])
        : "r"(a[0]), "r"(a[1]), "r"(a[2]), "r"(a[3]), "r"(b[0]), "r"(b[1]));
}

// Out[32][512] = Xs[32][512] @ Wg[512,512]^T + bg  (tf32 tensor-core path).
// 16 warps; warp w owns cols [w*32, w*32+32), all 32 rows.
// A frags from smem (Xs), B frags straight from global W (L2/L1 resident),
// register double-buffered across k8 steps; no block barriers in the K loop.
__device__ __noinline__ void gemm32(const float* __restrict__ Xs, const float* __restrict__ Wg,
                                    const float* __restrict__ bg, float* __restrict__ Out,
                                    int tid, bool relu)
{
    const int w = tid >> 5, lane = tid & 31;
    const int gid = lane >> 2, tig = lane & 3;
    const int n0 = w * 32;

    float d[2][4][4];
#pragma unroll
    for (int mf = 0; mf < 2; mf++)
#pragma unroll
        for (int nf = 0; nf < 4; nf++)
#pragma unroll
            for (int q = 0; q < 4; q++) d[mf][nf][q] = 0.f;

    // raw fp32 operand buffers (double-buffered); cvt at consume time
    float af[2][8], bf[2][8];

    // per-thread base pointers
    const float* xb0 = Xs + gid * LD + tig;              // mf=0 rows
    const float* wb[4];
#pragma unroll
    for (int nf = 0; nf < 4; nf++)
        wb[nf] = Wg + (size_t)(n0 + nf * 8 + gid) * C_NUM + tig;

    // prefetch k0 = 0
#pragma unroll
    for (int mf = 0; mf < 2; mf++) {
        const float* xb = xb0 + mf * 16 * LD;
        af[0][mf * 4 + 0] = xb[0];
        af[0][mf * 4 + 1] = xb[8 * LD];
        af[0][mf * 4 + 2] = xb[4];
        af[0][mf * 4 + 3] = xb[8 * LD + 4];
    }
#pragma unroll
    for (int nf = 0; nf < 4; nf++) {
        bf[0][nf * 2 + 0] = wb[nf][0];
        bf[0][nf * 2 + 1] = wb[nf][4];
    }

#pragma unroll 4
    for (int k0 = 0; k0 < C_NUM; k0 += 8) {
        const int p = (k0 >> 3) & 1;
        if (k0 + 8 < C_NUM) {
            const int kn = k0 + 8;
#pragma unroll
            for (int mf = 0; mf < 2; mf++) {
                const float* xb = xb0 + mf * 16 * LD + kn;
                af[p ^ 1][mf * 4 + 0] = xb[0];
                af[p ^ 1][mf * 4 + 1] = xb[8 * LD];
                af[p ^ 1][mf * 4 + 2] = xb[4];
                af[p ^ 1][mf * 4 + 3] = xb[8 * LD + 4];
            }
#pragma unroll
            for (int nf = 0; nf < 4; nf++) {
                bf[p ^ 1][nf * 2 + 0] = wb[nf][kn];
                bf[p ^ 1][nf * 2 + 1] = wb[nf][kn + 4];
            }
        }
        unsigned at[8], bt[8];
#pragma unroll
        for (int q = 0; q < 8; q++) at[q] = cvt_tf32(af[p][q]);
#pragma unroll
        for (int q = 0; q < 8; q++) bt[q] = cvt_tf32(bf[p][q]);
#pragma unroll
        for (int mf = 0; mf < 2; mf++)
#pragma unroll
            for (int nf = 0; nf < 4; nf++)
                mma_tf32(d[mf][nf], at + mf * 4, bt + nf * 2);
    }

    // epilogue: D(gid,2tig)/(gid,2tig+1)/(gid+8,..) per frag; add bias, optional relu
#pragma unroll
    for (int mf = 0; mf < 2; mf++)
#pragma unroll
        for (int nf = 0; nf < 4; nf++) {
            int col = n0 + nf * 8 + 2 * tig;
            float bb0 = bg[col], bb1 = bg[col + 1];
            int r0 = mf * 16 + gid, r1 = r0 + 8;
            float v00 = d[mf][nf][0] + bb0, v01 = d[mf][nf][1] + bb1;
            float v10 = d[mf][nf][2] + bb0, v11 = d[mf][nf][3] + bb1;
            if (relu) {
                v00 = fmaxf(v00, 0.f); v01 = fmaxf(v01, 0.f);
                v10 = fmaxf(v10, 0.f); v11 = fmaxf(v11, 0.f);
            }
            *reinterpret_cast<float2*>(Out + r0 * LD + col) = make_float2(v00, v01);
            *reinterpret_cast<float2*>(Out + r1 * LD + col) = make_float2(v10, v11);
        }
    __syncthreads();
}

// scores[h][i][j] = dot(Q[i,h*128:],K[j,:])/sqrt(128); mask j>=ylen; softmax over j.
__device__ __noinline__ void sab_scores_softmax(const float* __restrict__ Q, const float* __restrict__ K,
                                                float* __restrict__ S, int ylen, int tid)
{
    const float scale = 0.08838834764831845f;  // 1/sqrt(128)
#pragma unroll
    for (int it = 0; it < 8; it++) {
        int idx = tid + it * NT;               // h*1024 + i*32 + j
        int h = idx >> 10, i = (idx >> 5) & 31, j = idx & 31;
        const ulonglong2* q2 = reinterpret_cast<const ulonglong2*>(Q + i * LD + h * DH);
        const ulonglong2* k2 = reinterpret_cast<const ulonglong2*>(K + j * LD + h * DH);
        u64 a0 = 0ull, a1 = 0ull;
#pragma unroll
        for (int d = 0; d < DH / 4; d++) {
            ulonglong2 qa = q2[d], kb = k2[d];
            ffma2(a0, qa.x, kb.x);
            ffma2(a1, qa.y, kb.y);
        }
        S[idx] = (hadd2(a0) + hadd2(a1)) * scale;
    }
    __syncthreads();
    if (tid < H_NUM * L_NUM) {
        float* row = S + tid * L_NUM;          // tid = h*32 + i
        float mx = -1e30f;
        for (int j = 0; j < ylen; j++) mx = fmaxf(mx, row[j]);
        float sum = 0.f;
        for (int j = 0; j < L_NUM; j++) {
            float e = (j < ylen) ? __expf(row[j] - mx) : 0.f;
            row[j] = e; sum += e;
        }
        float inv = 1.f / sum;
        for (int j = 0; j < L_NUM; j++) row[j] *= inv;
    }
    __syncthreads();
}

// Out[i][c] = sum_j S[h(c)][i][j] * V[j][c]
__device__ __noinline__ void attn_v(const float* __restrict__ S, const float* __restrict__ V,
                                    float* __restrict__ Out, int ylen, int tid)
{
    const int rg = tid >> 7, cg = tid & 127;
    float acc[8][4];
#pragma unroll
    for (int a = 0; a < 8; a++)
#pragma unroll
        for (int b = 0; b < 4; b++) acc[a][b] = 0.f;

    for (int jk = 0; jk < ylen; jk++) {
        float vv[4];
#pragma unroll
        for (int jj = 0; jj < 4; jj++) vv[jj] = V[jk * LD + cg + 128 * jj];
        float sv[H_NUM][8];
#pragma unroll
        for (int h = 0; h < H_NUM; h++)
#pragma unroll
            for (int ii = 0; ii < 8; ii++)
                sv[h][ii] = S[h * (L_NUM * L_NUM) + (rg * 8 + ii) * L_NUM + jk];
#pragma unroll
        for (int jj = 0; jj < 4; jj++) {       // h = (cg+128*jj)>>7 == jj (cg<128)
#pragma unroll
            for (int ii = 0; ii < 8; ii++)
                acc[ii][jj] = fmaf(sv[jj][ii], vv[jj], acc[ii][jj]);
        }
    }
#pragma unroll
    for (int jj = 0; jj < 4; jj++)
#pragma unroll
        for (int ii = 0; ii < 8; ii++)
            Out[(rg * 8 + ii) * LD + cg + 128 * jj] = acc[ii][jj];
    __syncthreads();
}

// X[i] = LN(X[i] + (i<xm ? Y[i] : 0)) rowwise with gamma/beta
__device__ __noinline__ void sab_add_ln(float* __restrict__ X, const float* __restrict__ Y,
                                        const float* __restrict__ g, const float* __restrict__ b,
                                        int xm, int tid)
{
    const int w = tid >> 5, lane = tid & 31;
    for (int row = w; row < L_NUM; row += 16) {
        const float* yr = Y + row * LD;
        float* xr = X + row * LD;
        bool useY = row < xm;
        float s = 0.f, s2 = 0.f;
        for (int c = lane; c < C_NUM; c += 32) {
            float v = xr[c] + (useY ? yr[c] : 0.f);
            s += v; s2 += v * v;
        }
        s = warp_sum(s); s2 = warp_sum(s2);
        float mean = s * (1.f / C_NUM);
        float var = s2 * (1.f / C_NUM) - mean * mean;
        float rstd = rsqrtf(var + LN_EPS);
        for (int c = lane; c < C_NUM; c += 32) {
            float v = xr[c] + (useY ? yr[c] : 0.f);
            xr[c] = (v - mean) * rstd * g[c] + b[c];
        }
    }
    __syncthreads();
}

__device__ __noinline__ void mab_sab(Smem* sm,
    const float* Wq, const float* Wk, const float* Wv, const float* Wo, const float* ffW,
    const float* bq, const float* bk, const float* bv, const float* bo, const float* ffb,
    const float* g1, const float* b1, const float* g2, const float* b2,
    int ylen, int xm, int tid)
{
    gemm32(sm->X, Wq, bq, sm->A, tid, false);             // Q -> A
    gemm32(sm->X, Wk, bk, sm->B, tid, false);             // K -> B
    sab_scores_softmax(sm->A, sm->B, sm->S, ylen, tid);   // attn -> S
    gemm32(sm->X, Wv, bv, sm->B, tid, false);             // V -> B (K dead)
    attn_v(sm->S, sm->B, sm->A, ylen, tid);               // attn@V -> A (Q dead)
    gemm32(sm->A, Wo, bo, sm->B, tid, false);             // O -> B
    sab_add_ln(sm->X, sm->B, g1, b1, xm, tid);            // X = LN(X + mask(O))
    gemm32(sm->X, ffW, ffb, sm->A, tid, true);            // relu FF -> A
    sab_add_ln(sm->X, sm->A, g2, b2, L_NUM, tid);         // X = LN(X + FF)
}

// out[j] = sum_k xin[k]*Wg[j][k] + bg[j]   (xin: smem [512]); one j per thread
__device__ __noinline__ void vec_gemm(const float* __restrict__ xin, const float* __restrict__ Wg,
                                      const float* __restrict__ bg, float* __restrict__ out,
                                      int tid, bool relu)
{
    const ulonglong2* x2 = reinterpret_cast<const ulonglong2*>(xin);
    int j = tid;                               // NT == C_NUM
    const ulonglong2* w2 = reinterpret_cast<const ulonglong2*>(Wg + (size_t)j * C_NUM);
    u64 a0 = 0ull, a1 = 0ull;
#pragma unroll 8
    for (int d = 0; d < C_NUM / 4; d++) {
        ulonglong2 w = w2[d], x = x2[d];
        ffma2(a0, w.x, x.x);
        ffma2(a1, w.y, x.y);
    }
    float v = hadd2(a0) + hadd2(a1) + bg[j];
    if (relu) v = fmaxf(v, 0.f);
    out[j] = v;
    __syncthreads();
}

// x = LN(x + y) over a single 512-vector (block-wide, 16 warps)
__device__ __noinline__ void vec_add_ln(float* __restrict__ x, const float* __restrict__ y,
                                        const float* __restrict__ g, const float* __restrict__ b,
                                        float* __restrict__ red, int tid)
{
    float s = 0.f, s2 = 0.f;
    for (int c = tid; c < C_NUM; c += NT) {
        float v = x[c] + y[c]; s += v; s2 += v * v;
    }
    s = warp_sum(s); s2 = warp_sum(s2);
    int w = tid >> 5, lane = tid & 31;
    if (lane == 0) { red[w] = s; red[16 + w] = s2; }
    __syncthreads();
    if (tid == 0) {
        float ts = 0, ts2 = 0;
        for (int i = 0; i < 16; i++) { ts += red[i]; ts2 += red[16 + i]; }
        float mean = ts * (1.f / C_NUM);
        float var = ts2 * (1.f / C_NUM) - mean * mean;
        red[32] = mean; red[33] = rsqrtf(var + LN_EPS);
    }
    __syncthreads();
    float mean = red[32], rstd = red[33];
    for (int c = tid; c < C_NUM; c += NT) {
        float v = x[c] + y[c];
        x[c] = (v - mean) * rstd * g[c] + b[c];
    }
    __syncthreads();
}

// PMA attention: q (smem [512]) over K=sm->A [32,512], V=sm->B; out -> outv [512]
__device__ __noinline__ void pma_attn(Smem* sm, const float* __restrict__ q,
                                      float* __restrict__ psc, float* __restrict__ outv,
                                      int ylen, int tid)
{
    const float scale = 0.08838834764831845f;
    if (tid < H_NUM * L_NUM) {
        int h = tid >> 5, j = tid & 31;
        if (j < ylen) {
            const ulonglong2* q2 = reinterpret_cast<const ulonglong2*>(q + h * DH);
            const ulonglong2* k2 = reinterpret_cast<const ulonglong2*>(sm->A + j * LD + h * DH);
            u64 a0 = 0ull, a1 = 0ull;
#pragma unroll
            for (int d = 0; d < DH / 4; d++) {
                ulonglong2 qa = q2[d], kb = k2[d];
                ffma2(a0, qa.x, kb.x);
                ffma2(a1, qa.y, kb.y);
            }
            psc[h * L_NUM + j] = (hadd2(a0) + hadd2(a1)) * scale;
        }
    }
    __syncthreads();
    if (tid < H_NUM) {
        float* row = psc + tid * L_NUM;
        float mx = -1e30f;
        for (int j = 0; j < ylen; j++) mx = fmaxf(mx, row[j]);
        float sum = 0.f;
        for (int j = 0; j < ylen; j++) { float e = __expf(row[j] - mx); row[j] = e; sum += e; }
        float inv = 1.f / sum;
        for (int j = 0; j < ylen; j++) row[j] *= inv;
    }
    __syncthreads();
    for (int c = tid; c < C_NUM; c += NT) {
        int h = c >> 7;
        float s = 0.f;
        for (int j = 0; j < ylen; j++) s = fmaf(psc[h * L_NUM + j], sm->B[j * LD + c], s);
        outv[c] = s;
    }
    __syncthreads();
}

__global__ void __launch_bounds__(NT, 1)
rxn_set_transformer_kernel(
    const float* __restrict__ emb, const int* __restrict__ gidx, const int* __restrict__ glen,
    const float* __restrict__ Wq, const float* __restrict__ Wk, const float* __restrict__ Wv,
    const float* __restrict__ Wo, const float* __restrict__ ffW,
    const float* __restrict__ bq, const float* __restrict__ bk, const float* __restrict__ bv,
    const float* __restrict__ bo, const float* __restrict__ ffb,
    const float* __restrict__ g1, const float* __restrict__ b1,
    const float* __restrict__ g2, const float* __restrict__ b2,
    const float* __restrict__ pW, const float* __restrict__ pb,
    const float* __restrict__ seed, float* __restrict__ out)
{
    extern __shared__ char smem_raw[];
    Smem* sm = reinterpret_cast<Smem*>(smem_raw);
    const int tid = threadIdx.x;
    const int r = blockIdx.x;
    if (r >= R_NUM) return;

    int len = glen[r];
    if (len > L_NUM) len = L_NUM;
    if (len < 0) len = 0;

    // Gather + mask: X[i][c] = (i<len) ? emb[gidx[r,i]][c] : 0
#pragma unroll 4
    for (int it = 0; it < (L_NUM * C_NUM) / NT; it++) {
        int idx = tid + it * NT;
        int i = idx >> 9, c = idx & (C_NUM - 1);
        float v = 0.f;
        if (i < len) v = emb[(size_t)gidx[r * L_NUM + i] * C_NUM + c];
        sm->X[i * LD + c] = v;
    }
    __syncthreads();

    // Encoder SABs 0,1 (y_mask & x_mask = len)
    for (int blk = 0; blk < 2; blk++) {
        mab_sab(sm,
                Wq + blk * CC, Wk + blk * CC, Wv + blk * CC, Wo + blk * CC, ffW + blk * CC,
                bq + blk * C_NUM, bk + blk * C_NUM, bv + blk * C_NUM, bo + blk * C_NUM, ffb + blk * C_NUM,
                g1 + blk * C_NUM, b1 + blk * C_NUM, g2 + blk * C_NUM, b2 + blk * C_NUM,
                len, len, tid);
    }

    // y = relu(X @ pW^T + pb); copy back into X
    gemm32(sm->X, pW, pb, sm->A, tid, true);
#pragma unroll 4
    for (int it = 0; it < (L_NUM * C_NUM) / NT; it++) {
        int idx = tid + it * NT;
        int i = idx >> 9, c = idx & (C_NUM - 1);
        sm->X[i * LD + c] = sm->A[i * LD + c];
    }
    __syncthreads();

    // PMA (block 2): seed (1 query) attends over X with y_mask=len, x_mask=None.
    float* psc = sm->S;            // 128 floats
    float* xs  = sm->S + 512;      // current 1-token state
    float* vq  = sm->S + 1024;     // temp
    float* vt  = sm->S + 1536;     // temp
    for (int c = tid; c < C_NUM; c += NT) xs[c] = seed[c];
    __syncthreads();

    vec_gemm(xs, Wq + 2 * CC, bq + 2 * C_NUM, vq, tid, false);        // q
    gemm32(sm->X, Wk + 2 * CC, bk + 2 * C_NUM, sm->A, tid, false);    // K
    gemm32(sm->X, Wv + 2 * CC, bv + 2 * C_NUM, sm->B, tid, false);    // V
    pma_attn(sm, vq, psc, vt, len, tid);                              // attn out -> vt
    vec_gemm(vt, Wo + 2 * CC, bo + 2 * C_NUM, vq, tid, false);        // O -> vq
    vec_add_ln(xs, vq, g1 + 2 * C_NUM, b1 + 2 * C_NUM, sm->red, tid); // xs = LN(seed + O)
    vec_gemm(xs, ffW + 2 * CC, ffb + 2 * C_NUM, vt, tid, true);       // relu FF -> vt
    vec_add_ln(xs, vt, g2 + 2 * C_NUM, b2 + 2 * C_NUM, sm->red, tid);

    // Decoder SAB (block 3) on one token: softmax over 1 key == 1 -> out == v.
    vec_gemm(xs, Wv + 3 * CC, bv + 3 * C_NUM, vq, tid, false);        // v
    vec_gemm(vq, Wo + 3 * CC, bo + 3 * C_NUM, vt, tid, false);        // O
    vec_add_ln(xs, vt, g1 + 3 * C_NUM, b1 + 3 * C_NUM, sm->red, tid);
    vec_gemm(xs, ffW + 3 * CC, ffb + 3 * C_NUM, vq, tid, true);       // relu FF
    vec_add_ln(xs, vq, g2 + 3 * C_NUM, b2 + 3 * C_NUM, sm->red, tid);

    // out[r] = xs (mean over 1 seed), zeroed if empty reaction
    for (int c = tid; c < C_NUM; c += NT)
        out[(size_t)r * C_NUM + c] = (len > 0) ? xs[c] : 0.f;
}

extern "C" void kernel_launch(void* const* d_in, const int* in_sizes, int n_in,
                              void* d_out, int out_size)
{
    const float* emb  = (const float*)d_in[0];
    const int*   gidx = (const int*)d_in[1];
    const int*   glen = (const int*)d_in[2];
    const float* Wq   = (const float*)d_in[3];
    const float* Wk   = (const float*)d_in[4];
    const float* Wv   = (const float*)d_in[5];
    const float* Wo   = (const float*)d_in[6];
    const float* ffW  = (const float*)d_in[7];
    const float* bq   = (const float*)d_in[8];
    const float* bk   = (const float*)d_in[9];
    const float* bv   = (const float*)d_in[10];
    const float* bo   = (const float*)d_in[11];
    const float* ffb  = (const float*)d_in[12];
    const float* g1   = (const float*)d_in[13];
    const float* b1   = (const float*)d_in[14];
    const float* g2   = (const float*)d_in[15];
    const float* b2   = (const float*)d_in[16];
    const float* pW   = (const float*)d_in[17];
    const float* pb   = (const float*)d_in[18];
    const float* seed = (const float*)d_in[19];

    (void)in_sizes; (void)n_in; (void)out_size;

    cudaFuncSetAttribute(rxn_set_transformer_kernel,
                         cudaFuncAttributeMaxDynamicSharedMemorySize,
                         (int)sizeof(Smem));

    rxn_set_transformer_kernel<<<R_NUM, NT, sizeof(Smem)>>>(
        emb, gidx, glen, Wq, Wk, Wv, Wo, ffW,
        bq, bk, bv, bo, ffb, g1, b1, g2, b2,
        pW, pb, seed, (float*)d_out);
}